// round 10
// baseline (speedup 1.0000x reference)
#include <cuda_runtime.h>

// ---------------- problem constants ----------------
#define NV 16384
#define NC 8192
#define NE 65536
#define BB 1024
#define B4 256            // BB/4 float4 per row
#define CLIPV 15.0f
#define EPSF 1e-6f
#define ABS_MIN 6.1180464e-07f   // -log(tanh(15/2))

#define DV_REG 4          // reg-cached edges per variable
#define DC_SMEM 12        // smem-cached edges per check
#define NTILE 4
#define TW 64             // float4 columns per tile (256 floats)

// ---------------- scratch (static device globals) ----------------
__device__ int g_cntV[NV];
__device__ int g_cntC[NC];
__device__ int g_rowV[NV + 1];
__device__ int g_rowC[NC + 1];
__device__ int g_curV[NV];
__device__ int g_curC[NC];
__device__ int g_edgeV[NE];
__device__ int g_edgeC[NE];

// log(tanh(x/2)), x in [ABS_MIN, 15]  (always < 0)
__device__ __forceinline__ float logtanh_half(float x) {
    if (x > 0.5f) {
        float u = __expf(-x);                        // u <= 0.607
        return __logf(__fdividef(1.0f - u, 1.0f + u));
    } else {
        // log(x/2) - x^2/12 + 7*(x/2)^4/90  (abs err < 6e-6 on [0, 0.5])
        float z = 0.5f * x;
        float z2 = z * z;
        return __logf(z) + z2 * (-0.33333333f + z2 * 0.07777778f);
    }
}

__device__ __forceinline__ void red_add_v4(float* p, float4 v) {
    asm volatile("red.global.add.v4.f32 [%0], {%1, %2, %3, %4};"
                 :: "l"(p), "f"(v.x), "f"(v.y), "f"(v.z), "f"(v.w) : "memory");
}

// ---------------- CSR build ----------------
__global__ void __launch_bounds__(256) kCount(const int* __restrict__ vi,
                                              const int* __restrict__ ci)
{
    int e = blockIdx.x * 256 + threadIdx.x;
    if (e < NE) {
        atomicAdd(&g_cntV[__ldg(vi + e)], 1);
        atomicAdd(&g_cntC[__ldg(ci + e)], 1);
    }
}

__global__ void __launch_bounds__(1024) kScan()
{
    const bool isV = (blockIdx.x == 0);
    const int N = isV ? NV : NC;
    int* cnt = isV ? g_cntV : g_cntC;
    int* row = isV ? g_rowV : g_rowC;
    int* cur = isV ? g_curV : g_curC;
    const int CH = N / 1024;
    int t = threadIdx.x;
    int base = t * CH;
    int local[16];
    int s = 0;
    for (int i = 0; i < CH; i++) { local[i] = s; s += cnt[base + i]; }
    __shared__ int sm[1024];
    sm[t] = s;
    __syncthreads();
    for (int d = 1; d < 1024; d <<= 1) {
        int x = (t >= d) ? sm[t - d] : 0;
        __syncthreads();
        sm[t] += x;
        __syncthreads();
    }
    int excl = (t == 0) ? 0 : sm[t - 1];
    for (int i = 0; i < CH; i++) {
        row[base + i] = excl + local[i];
        cur[base + i] = excl + local[i];
    }
    if (t == 1023) row[N] = sm[1023];
}

__global__ void __launch_bounds__(256) kFill(const int* __restrict__ vi,
                                             const int* __restrict__ ci)
{
    int e = blockIdx.x * 256 + threadIdx.x;
    if (e < NE) {
        int p = atomicAdd(&g_curV[__ldg(vi + e)], 1);
        g_edgeV[p] = e;
        int q = atomicAdd(&g_curC[__ldg(ci + e)], 1);
        g_edgeC[q] = e;
    }
}

// ---------------- V step on one column strip ----------------
// block (TW, 2): 2 variables per block
__global__ void __launch_bounds__(128) kV(
    const float4* __restrict__ chn, const float4* __restrict__ mc2v,
    const float4* __restrict__ mv2c,
    const float* __restrict__ Wi_p, const float* __restrict__ We_p,
    const float* __restrict__ gm_p,
    float4* __restrict__ outV2C, float4* __restrict__ outM, int col0)
{
    int v = blockIdx.x * 2 + threadIdx.y;
    int col = col0 + threadIdx.x;               // float4 column
    int s = __ldg(&g_rowV[v]), e1 = __ldg(&g_rowV[v + 1]);
    int deg = e1 - s;

    float Wi = __ldg(Wi_p), We = __ldg(We_p), g = __ldg(gm_p);
    float omg = 1.0f - g;
    float4 ch = __ldcs(chn + (size_t)v * B4 + col);

    // init marginal output (REDs from kH accumulate on top)
    outM[(size_t)v * B4 + col] =
        make_float4(Wi * ch.x, Wi * ch.y, Wi * ch.z, Wi * ch.w);
    if (deg == 0) return;

    float4 mreg[DV_REG];
    float sx = 0.f, sy = 0.f, sz = 0.f, sw = 0.f;
    #pragma unroll 4
    for (int j = 0; j < deg; j++) {
        int e = __ldg(&g_edgeV[s + j]);
        float4 m = __ldg(mc2v + (size_t)e * B4 + col);
        if (j < DV_REG) mreg[j] = m;
        sx += m.x; sy += m.y; sz += m.z; sw += m.w;
    }

    float ellx = Wi * ch.x, elly = Wi * ch.y, ellz = Wi * ch.z, ellw = Wi * ch.w;

    #pragma unroll 4
    for (int j = 0; j < deg; j++) {
        int e = __ldg(&g_edgeV[s + j]);
        float4 m = (j < DV_REG) ? mreg[j]
                                : __ldg(mc2v + (size_t)e * B4 + col); // L1 hit
        float4 mv = __ldcs(mv2c + (size_t)e * B4 + col);
        float4 o;
        o.x = omg * mv.x + g * (ellx + We * (sx - m.x));
        o.y = omg * mv.y + g * (elly + We * (sy - m.y));
        o.z = omg * mv.z + g * (ellz + We * (sz - m.z));
        o.w = omg * mv.w + g * (ellw + We * (sw - m.w));
        outV2C[(size_t)e * B4 + col] = o;
    }
}

// ---------------- H step on one column strip ----------------
// block (TW, 2): 2 checks per block; log-domain, smem cache, RED into outM
__global__ void __launch_bounds__(128) kH(
    const float4* __restrict__ v2cNew, const float4* __restrict__ mc2v,
    const int* __restrict__ vi,
    const float* __restrict__ We_p, const float* __restrict__ gm_p,
    float4* __restrict__ outC2V, float* __restrict__ outM, int col0)
{
    int c = blockIdx.x * 2 + threadIdx.y;
    int col = col0 + threadIdx.x;
    int s = __ldg(&g_rowC[c]), e1 = __ldg(&g_rowC[c + 1]);
    int deg = e1 - s;
    if (deg == 0) return;

    __shared__ float4 senc[2][DC_SMEM][TW];   // 24 KB: -lt, sign bit = neg

    float We = __ldg(We_p), g = __ldg(gm_p);
    float omg = 1.0f - g;

    float Slt[4] = {0.f, 0.f, 0.f, 0.f};
    int   Sng[4] = {0, 0, 0, 0};

    #pragma unroll 2
    for (int j = 0; j < deg; j++) {
        int e = __ldg(&g_edgeC[s + j]);
        float4 l4 = __ldg(v2cNew + (size_t)e * B4 + col);
        float lam[4] = {l4.x, l4.y, l4.z, l4.w};
        float enc[4];
        #pragma unroll
        for (int i = 0; i < 4; i++) {
            float lm = fminf(fmaxf(lam[i], -CLIPV), CLIPV);
            int ng = (lm < 0.f) ? 1 : 0;
            float al = fminf(fmaxf(fabsf(lm), ABS_MIN), CLIPV);
            float lt = logtanh_half(al);           // < 0
            Slt[i] += lt;
            Sng[i] += ng;
            enc[i] = ng ? lt : -lt;                // sign bit = ng
        }
        if (j < DC_SMEM)
            senc[threadIdx.y][j][threadIdx.x] =
                make_float4(enc[0], enc[1], enc[2], enc[3]);
    }

    #pragma unroll 2
    for (int j = 0; j < deg; j++) {
        int e = __ldg(&g_edgeC[s + j]);
        int v = __ldg(vi + e);
        float lt[4]; int ng[4];
        if (j < DC_SMEM) {
            float4 e4 = senc[threadIdx.y][j][threadIdx.x];
            float enc[4] = {e4.x, e4.y, e4.z, e4.w};
            #pragma unroll
            for (int i = 0; i < 4; i++) {
                ng[i] = (enc[i] < 0.f) ? 1 : 0;
                lt[i] = -fabsf(enc[i]);
            }
        } else {
            float4 l4 = __ldg(v2cNew + (size_t)e * B4 + col);  // L1 hit
            float lam[4] = {l4.x, l4.y, l4.z, l4.w};
            #pragma unroll
            for (int i = 0; i < 4; i++) {
                float lm = fminf(fmaxf(lam[i], -CLIPV), CLIPV);
                ng[i] = (lm < 0.f) ? 1 : 0;
                float al = fminf(fmaxf(fabsf(lm), ABS_MIN), CLIPV);
                lt[i] = logtanh_half(al);
            }
        }

        float4 mc = __ldcs(mc2v + (size_t)e * B4 + col);
        float mcs[4] = {mc.x, mc.y, mc.z, mc.w};
        float os[4];
        #pragma unroll
        for (int i = 0; i < 4; i++) {
            float amp = fminf(Slt[i] - lt[i], 0.0f);
            int cnt = Sng[i] - ng[i];
            float y = __expf(amp) * (1.0f - EPSF);
            float h = __logf(__fdividef(1.0f + y, 1.0f - y));   // >= 0
            unsigned hu = __float_as_uint(h) ^ ((unsigned)(cnt & 1) << 31);
            os[i] = omg * mcs[i] + g * __uint_as_float(hu);
        }
        float4 o = make_float4(os[0], os[1], os[2], os[3]);
        __stcs(outC2V + (size_t)e * B4 + col, o);

        float* dst = outM + (size_t)v * BB + col * 4;
        red_add_v4(dst, make_float4(We * o.x, We * o.y, We * o.z, We * o.w));
    }
}

// ---------------- stream/event context (created once, outside capture) ----
struct Ctx {
    cudaStream_t s1;
    cudaEvent_t evV[NTILE];
    cudaEvent_t evEnd;
    Ctx() {
        cudaStreamCreateWithFlags(&s1, cudaStreamNonBlocking);
        for (int t = 0; t < NTILE; t++)
            cudaEventCreateWithFlags(&evV[t], cudaEventDisableTiming);
        cudaEventCreateWithFlags(&evEnd, cudaEventDisableTiming);
    }
};
static Ctx& ctx() { static Ctx c; return c; }

// ---------------- launch ----------------
extern "C" void kernel_launch(void* const* d_in, const int* in_sizes, int n_in,
                              void* d_out, int out_size)
{
    (void)in_sizes; (void)n_in; (void)out_size;

    const float* chn  = (const float*)d_in[0];
    const float* mc2v = (const float*)d_in[1];
    const float* mv2c = (const float*)d_in[2];
    const float* Wi   = (const float*)d_in[3];
    const float* We   = (const float*)d_in[4];
    const float* gm   = (const float*)d_in[5];
    const int*   vi   = (const int*)d_in[6];
    const int*   ci   = (const int*)d_in[7];

    // outputs: (msg_C2V, msg_V2C, output)
    float* outC2V = (float*)d_out;
    float* outV2C = outC2V + (size_t)NE * BB;
    float* outM   = outV2C + (size_t)NE * BB;

    Ctx& C = ctx();

    void *pcv, *pcc;
    cudaGetSymbolAddress(&pcv, g_cntV);
    cudaGetSymbolAddress(&pcc, g_cntC);
    cudaMemsetAsync(pcv, 0, sizeof(int) * NV, 0);
    cudaMemsetAsync(pcc, 0, sizeof(int) * NC, 0);

    kCount<<<NE / 256, 256>>>(vi, ci);
    kScan<<<2, 1024>>>();
    kFill<<<NE / 256, 256>>>(vi, ci);

    dim3 blk(TW, 2);
    for (int t = 0; t < NTILE; t++) {
        int col0 = t * TW;
        kV<<<NV / 2, blk, 0, 0>>>((const float4*)chn, (const float4*)mc2v,
                                  (const float4*)mv2c, Wi, We, gm,
                                  (float4*)outV2C, (float4*)outM, col0);
        cudaEventRecord(C.evV[t], 0);
        cudaStreamWaitEvent(C.s1, C.evV[t], 0);
        kH<<<NC / 2, blk, 0, C.s1>>>((const float4*)outV2C,
                                     (const float4*)mc2v, vi, We, gm,
                                     (float4*)outC2V, outM, col0);
    }
    cudaEventRecord(C.evEnd, C.s1);
    cudaStreamWaitEvent(0, C.evEnd, 0);
}

// round 11
// speedup vs baseline: 1.0566x; 1.0566x over previous
#include <cuda_runtime.h>

// ---------------- problem constants ----------------
#define NV 16384
#define NC 8192
#define NE 65536
#define BB 1024
#define B4 256            // BB/4 float4 per row
#define CLIPV 15.0f
#define EPSP 1.0000005e-6f   // -log(1 - 1e-6): exact fold of ref's (1-eps)
#define ABS_MIN 6.1180464e-07f   // -log(tanh(15/2))

#define DV_REG 4          // reg-cached edges per variable
#define DC_SMEM 10        // smem-cached edges per check (20 KB)

// ---------------- scratch (static device globals) ----------------
__device__ int g_cntV[NV];
__device__ int g_cntC[NC];
__device__ int g_rowV[NV + 1];
__device__ int g_rowC[NC + 1];
__device__ int g_curV[NV];
__device__ int g_curC[NC];
__device__ int g_edgeV[NE];
__device__ int g_edgeC[NE];

// log(tanh(x/2)), x > 0, 3 branches  (always < 0)
__device__ __forceinline__ float logtanh3(float x) {
    if (x <= 0.5f) {
        // log(x/2) - (x/2)^2/3 + 7(x/2)^4/90   (abs err < 6e-6)
        float z = 0.5f * x;
        float z2 = z * z;
        return __logf(z) + z2 * (-0.33333333f + z2 * 0.07777778f);
    } else if (x < 9.0f) {
        float u = __expf(-x);                        // u in (1.2e-4, 0.607)
        return __logf(__fdividef(1.0f - u, 1.0f + u));
    } else {
        // -2u(1 + u^2/3), u = e^-x <= 1.2e-4  (abs err < 1e-12)
        float u = __expf(-x);
        return -2.0f * u * (1.0f + 0.33333333f * u * u);
    }
}

__device__ __forceinline__ void red_add_v4(float* p, float4 v) {
    asm volatile("red.global.add.v4.f32 [%0], {%1, %2, %3, %4};"
                 :: "l"(p), "f"(v.x), "f"(v.y), "f"(v.z), "f"(v.w) : "memory");
}

// ---------------- CSR build ----------------
__global__ void __launch_bounds__(256) kCount(const int* __restrict__ vi,
                                              const int* __restrict__ ci)
{
    int e = blockIdx.x * 256 + threadIdx.x;
    if (e < NE) {
        atomicAdd(&g_cntV[__ldg(vi + e)], 1);
        atomicAdd(&g_cntC[__ldg(ci + e)], 1);
    }
}

__global__ void __launch_bounds__(1024) kScan()
{
    const bool isV = (blockIdx.x == 0);
    const int N = isV ? NV : NC;
    int* cnt = isV ? g_cntV : g_cntC;
    int* row = isV ? g_rowV : g_rowC;
    int* cur = isV ? g_curV : g_curC;
    const int CH = N / 1024;
    int t = threadIdx.x;
    int base = t * CH;
    int local[16];
    int s = 0;
    for (int i = 0; i < CH; i++) { local[i] = s; s += cnt[base + i]; }
    __shared__ int sm[1024];
    sm[t] = s;
    __syncthreads();
    for (int d = 1; d < 1024; d <<= 1) {
        int x = (t >= d) ? sm[t - d] : 0;
        __syncthreads();
        sm[t] += x;
        __syncthreads();
    }
    int excl = (t == 0) ? 0 : sm[t - 1];
    for (int i = 0; i < CH; i++) {
        row[base + i] = excl + local[i];
        cur[base + i] = excl + local[i];
    }
    if (t == 1023) row[N] = sm[1023];
}

__global__ void __launch_bounds__(256) kFill(const int* __restrict__ vi,
                                             const int* __restrict__ ci)
{
    int e = blockIdx.x * 256 + threadIdx.x;
    if (e < NE) {
        int p = atomicAdd(&g_curV[__ldg(vi + e)], 1);
        g_edgeV[p] = e;
        int q = atomicAdd(&g_curC[__ldg(ci + e)], 1);
        g_edgeC[q] = e;
    }
}

// ---------------- V step (also initializes outM = Wi*chn) ----------------
__global__ void __launch_bounds__(128) kV(
    const float4* __restrict__ chn, const float4* __restrict__ mc2v,
    const float4* __restrict__ mv2c,
    const float* __restrict__ Wi_p, const float* __restrict__ We_p,
    const float* __restrict__ gm_p,
    float4* __restrict__ outV2C, float4* __restrict__ outM)
{
    int v = blockIdx.x;
    int col = blockIdx.y * 128 + threadIdx.x;   // float4 column
    int s = __ldg(&g_rowV[v]), e1 = __ldg(&g_rowV[v + 1]);
    int deg = e1 - s;

    float Wi = __ldg(Wi_p), We = __ldg(We_p), g = __ldg(gm_p);
    float omg = 1.0f - g;
    float4 ch = __ldcs(chn + (size_t)v * B4 + col);

    // init marginal output (REDs from kH accumulate on top)
    outM[(size_t)v * B4 + col] =
        make_float4(Wi * ch.x, Wi * ch.y, Wi * ch.z, Wi * ch.w);
    if (deg == 0) return;

    float4 mreg[DV_REG];
    float sx = 0.f, sy = 0.f, sz = 0.f, sw = 0.f;
    #pragma unroll 4
    for (int j = 0; j < deg; j++) {
        int e = __ldg(&g_edgeV[s + j]);
        float4 m = __ldg(mc2v + (size_t)e * B4 + col);
        if (j < DV_REG) mreg[j] = m;
        sx += m.x; sy += m.y; sz += m.z; sw += m.w;
    }

    float ellx = Wi * ch.x, elly = Wi * ch.y, ellz = Wi * ch.z, ellw = Wi * ch.w;

    #pragma unroll 4
    for (int j = 0; j < deg; j++) {
        int e = __ldg(&g_edgeV[s + j]);
        float4 m = (j < DV_REG) ? mreg[j]
                                : __ldg(mc2v + (size_t)e * B4 + col); // L1 hit
        float4 mv = __ldcs(mv2c + (size_t)e * B4 + col);
        float4 o;
        o.x = omg * mv.x + g * (ellx + We * (sx - m.x));
        o.y = omg * mv.y + g * (elly + We * (sy - m.y));
        o.z = omg * mv.z + g * (ellz + We * (sz - m.z));
        o.w = omg * mv.w + g * (ellw + We * (sw - m.w));
        outV2C[(size_t)e * B4 + col] = o;
    }
}

// ---------------- H step: log-domain, identity pass2, smem cache ---------
__global__ void __launch_bounds__(128) kH(
    const float4* __restrict__ v2cNew, const float4* __restrict__ mc2v,
    const int* __restrict__ vi,
    const float* __restrict__ We_p, const float* __restrict__ gm_p,
    float4* __restrict__ outC2V, float* __restrict__ outM)
{
    int c = blockIdx.x;
    int col = blockIdx.y * 128 + threadIdx.x;
    int s = __ldg(&g_rowC[c]), e1 = __ldg(&g_rowC[c + 1]);
    int deg = e1 - s;
    if (deg == 0) return;

    __shared__ float4 senc[DC_SMEM][128];   // 20 KB: -lt, sign bit = neg flag

    float We = __ldg(We_p), g = __ldg(gm_p);
    float omg = 1.0f - g;

    float Slt[4] = {0.f, 0.f, 0.f, 0.f};
    int   Sng[4] = {0, 0, 0, 0};

    #pragma unroll 2
    for (int j = 0; j < deg; j++) {
        int e = __ldg(&g_edgeC[s + j]);
        float4 l4 = __ldg(v2cNew + (size_t)e * B4 + col);
        float lam[4] = {l4.x, l4.y, l4.z, l4.w};
        float enc[4];
        #pragma unroll
        for (int i = 0; i < 4; i++) {
            float lm = fminf(fmaxf(lam[i], -CLIPV), CLIPV);
            int ng = (lm < 0.f) ? 1 : 0;
            float al = fminf(fmaxf(fabsf(lm), ABS_MIN), CLIPV);
            float lt = logtanh3(al);               // < 0
            Slt[i] += lt;
            Sng[i] += ng;
            enc[i] = ng ? lt : -lt;                // sign bit = ng
        }
        if (j < DC_SMEM)
            senc[j][threadIdx.x] = make_float4(enc[0], enc[1], enc[2], enc[3]);
    }

    #pragma unroll 2
    for (int j = 0; j < deg; j++) {
        int e = __ldg(&g_edgeC[s + j]);
        int v = __ldg(vi + e);
        float lt[4]; int ng[4];
        if (j < DC_SMEM) {
            float4 e4 = senc[j][threadIdx.x];
            float enc[4] = {e4.x, e4.y, e4.z, e4.w};
            #pragma unroll
            for (int i = 0; i < 4; i++) {
                ng[i] = (enc[i] < 0.f) ? 1 : 0;
                lt[i] = -fabsf(enc[i]);
            }
        } else {
            float4 l4 = __ldg(v2cNew + (size_t)e * B4 + col);  // L1 hit
            float lam[4] = {l4.x, l4.y, l4.z, l4.w};
            #pragma unroll
            for (int i = 0; i < 4; i++) {
                float lm = fminf(fmaxf(lam[i], -CLIPV), CLIPV);
                ng[i] = (lm < 0.f) ? 1 : 0;
                float al = fminf(fmaxf(fabsf(lm), ABS_MIN), CLIPV);
                lt[i] = logtanh3(al);
            }
        }

        float4 mc = __ldcs(mc2v + (size_t)e * B4 + col);
        float mcs[4] = {mc.x, mc.y, mc.z, mc.w};
        float os[4];
        #pragma unroll
        for (int i = 0; i < 4; i++) {
            // a = -min(Slt - lt, 0) + eps'  ==>  h = -log(tanh(a/2))
            // identical to ref's  h = 2*atanh(exp(amp)*(1-1e-6))
            float a = fmaxf(lt[i] - Slt[i], 0.0f) + EPSP;
            int cnt = Sng[i] - ng[i];
            float h = -logtanh3(a);                 // >= 0
            unsigned hu = __float_as_uint(h) ^ ((unsigned)(cnt & 1) << 31);
            os[i] = omg * mcs[i] + g * __uint_as_float(hu);
        }
        float4 o = make_float4(os[0], os[1], os[2], os[3]);
        __stcs(outC2V + (size_t)e * B4 + col, o);

        float* dst = outM + (size_t)v * BB + col * 4;
        red_add_v4(dst, make_float4(We * o.x, We * o.y, We * o.z, We * o.w));
    }
}

// ---------------- launch ----------------
extern "C" void kernel_launch(void* const* d_in, const int* in_sizes, int n_in,
                              void* d_out, int out_size)
{
    (void)in_sizes; (void)n_in; (void)out_size;

    const float* chn  = (const float*)d_in[0];
    const float* mc2v = (const float*)d_in[1];
    const float* mv2c = (const float*)d_in[2];
    const float* Wi   = (const float*)d_in[3];
    const float* We   = (const float*)d_in[4];
    const float* gm   = (const float*)d_in[5];
    const int*   vi   = (const int*)d_in[6];
    const int*   ci   = (const int*)d_in[7];

    // outputs: (msg_C2V, msg_V2C, output)
    float* outC2V = (float*)d_out;
    float* outV2C = outC2V + (size_t)NE * BB;
    float* outM   = outV2C + (size_t)NE * BB;

    void *pcv, *pcc;
    cudaGetSymbolAddress(&pcv, g_cntV);
    cudaGetSymbolAddress(&pcc, g_cntC);
    cudaMemsetAsync(pcv, 0, sizeof(int) * NV, 0);
    cudaMemsetAsync(pcc, 0, sizeof(int) * NC, 0);

    kCount<<<NE / 256, 256>>>(vi, ci);
    kScan<<<2, 1024>>>();
    kFill<<<NE / 256, 256>>>(vi, ci);

    kV<<<dim3(NV, 2), 128>>>((const float4*)chn, (const float4*)mc2v,
                             (const float4*)mv2c, Wi, We, gm,
                             (float4*)outV2C, (float4*)outM);
    kH<<<dim3(NC, 2), 128>>>((const float4*)outV2C, (const float4*)mc2v,
                             vi, We, gm, (float4*)outC2V, outM);
}

// round 12
// speedup vs baseline: 1.1318x; 1.0712x over previous
#include <cuda_runtime.h>

// ---------------- problem constants ----------------
#define NV 16384
#define NC 8192
#define NE 65536
#define BB 1024
#define B4 256            // BB/4 float4 per row
#define CLIPV 15.0f
#define EPSF 1e-6f
#define ABS_MIN 6.1180464e-07f   // -log(tanh(15/2))

#define DV_REG 6          // reg-cached edges per variable
#define DC_SMEM 12        // smem-cached edges per check (24 KB)

// ---------------- scratch (static device globals) ----------------
__device__ int g_cntV[NV];
__device__ int g_cntC[NC];
__device__ int g_rowV[NV + 1];
__device__ int g_rowC[NC + 1];
__device__ int g_curV[NV];
__device__ int g_curC[NC];
__device__ int g_edgeV[NE];
__device__ int g_edgeC[NE];

// log(tanh(x/2)), x in [ABS_MIN, 15]  (always < 0) -- proven 3.05e-5 config
__device__ __forceinline__ float logtanh_half(float x) {
    if (x > 0.5f) {
        float u = __expf(-x);                        // u <= 0.607
        return __logf(__fdividef(1.0f - u, 1.0f + u));
    } else {
        // log(x/2) - x^2/12 + 7*(x/2)^4/90  (abs err < 6e-6 on [0, 0.5])
        float z = 0.5f * x;
        float z2 = z * z;
        return __logf(z) + z2 * (-0.33333333f + z2 * 0.07777778f);
    }
}

__device__ __forceinline__ void red_add_v4(float* p, float4 v) {
    asm volatile("red.global.add.v4.f32 [%0], {%1, %2, %3, %4};"
                 :: "l"(p), "f"(v.x), "f"(v.y), "f"(v.z), "f"(v.w) : "memory");
}

// ---------------- CSR build ----------------
__global__ void __launch_bounds__(256) kCount(const int* __restrict__ vi,
                                              const int* __restrict__ ci)
{
    int e = blockIdx.x * 256 + threadIdx.x;
    if (e < NE) {
        atomicAdd(&g_cntV[__ldg(vi + e)], 1);
        atomicAdd(&g_cntC[__ldg(ci + e)], 1);
    }
}

__global__ void __launch_bounds__(1024) kScan()
{
    const bool isV = (blockIdx.x == 0);
    const int N = isV ? NV : NC;
    int* cnt = isV ? g_cntV : g_cntC;
    int* row = isV ? g_rowV : g_rowC;
    int* cur = isV ? g_curV : g_curC;
    const int CH = N / 1024;
    int t = threadIdx.x;
    int base = t * CH;
    int local[16];
    int s = 0;
    for (int i = 0; i < CH; i++) { local[i] = s; s += cnt[base + i]; }
    __shared__ int sm[1024];
    sm[t] = s;
    __syncthreads();
    for (int d = 1; d < 1024; d <<= 1) {
        int x = (t >= d) ? sm[t - d] : 0;
        __syncthreads();
        sm[t] += x;
        __syncthreads();
    }
    int excl = (t == 0) ? 0 : sm[t - 1];
    for (int i = 0; i < CH; i++) {
        row[base + i] = excl + local[i];
        cur[base + i] = excl + local[i];
    }
    if (t == 1023) row[N] = sm[1023];
}

__global__ void __launch_bounds__(256) kFill(const int* __restrict__ vi,
                                             const int* __restrict__ ci)
{
    int e = blockIdx.x * 256 + threadIdx.x;
    if (e < NE) {
        int p = atomicAdd(&g_curV[__ldg(vi + e)], 1);
        g_edgeV[p] = e;
        int q = atomicAdd(&g_curC[__ldg(ci + e)], 1);
        g_edgeC[q] = e;
    }
}

// ---------------- V step (also initializes outM = Wi*chn) ----------------
__global__ void __launch_bounds__(128) kV(
    const float4* __restrict__ chn, const float4* __restrict__ mc2v,
    const float4* __restrict__ mv2c,
    const float* __restrict__ Wi_p, const float* __restrict__ We_p,
    const float* __restrict__ gm_p,
    float4* __restrict__ outV2C, float4* __restrict__ outM)
{
    int v = blockIdx.x;
    int col = blockIdx.y * 128 + threadIdx.x;   // float4 column
    int s = __ldg(&g_rowV[v]), e1 = __ldg(&g_rowV[v + 1]);
    int deg = e1 - s;

    float Wi = __ldg(Wi_p), We = __ldg(We_p), g = __ldg(gm_p);
    float omg = 1.0f - g;
    float4 ch = __ldcs(chn + (size_t)v * B4 + col);

    // init marginal output (REDs from kH accumulate on top)
    outM[(size_t)v * B4 + col] =
        make_float4(Wi * ch.x, Wi * ch.y, Wi * ch.z, Wi * ch.w);
    if (deg == 0) return;

    float4 mreg[DV_REG];
    float sx = 0.f, sy = 0.f, sz = 0.f, sw = 0.f;
    #pragma unroll 4
    for (int j = 0; j < deg; j++) {
        int e = __ldg(&g_edgeV[s + j]);
        float4 m = __ldg(mc2v + (size_t)e * B4 + col);
        if (j < DV_REG) mreg[j] = m;
        sx += m.x; sy += m.y; sz += m.z; sw += m.w;
    }

    float ellx = Wi * ch.x, elly = Wi * ch.y, ellz = Wi * ch.z, ellw = Wi * ch.w;

    #pragma unroll 4
    for (int j = 0; j < deg; j++) {
        int e = __ldg(&g_edgeV[s + j]);
        float4 m = (j < DV_REG) ? mreg[j]
                                : __ldg(mc2v + (size_t)e * B4 + col); // L1 hit
        float4 mv = __ldcs(mv2c + (size_t)e * B4 + col);
        float4 o;
        o.x = omg * mv.x + g * (ellx + We * (sx - m.x));
        o.y = omg * mv.y + g * (elly + We * (sy - m.y));
        o.z = omg * mv.z + g * (ellz + We * (sz - m.z));
        o.w = omg * mv.w + g * (ellw + We * (sw - m.w));
        outV2C[(size_t)e * B4 + col] = o;
    }
}

// ---------------- H step: R4 structure x R5 numerics ----------------
__global__ void __launch_bounds__(128) kH(
    const float4* __restrict__ v2cNew, const float4* __restrict__ mc2v,
    const int* __restrict__ vi,
    const float* __restrict__ We_p, const float* __restrict__ gm_p,
    float4* __restrict__ outC2V, float* __restrict__ outM)
{
    int c = blockIdx.x;
    int col = blockIdx.y * 128 + threadIdx.x;
    int s = __ldg(&g_rowC[c]), e1 = __ldg(&g_rowC[c + 1]);
    int deg = e1 - s;
    if (deg == 0) return;

    __shared__ float4 senc[DC_SMEM][128];   // 24 KB: -lt, sign bit = neg flag

    float We = __ldg(We_p), g = __ldg(gm_p);
    float omg = 1.0f - g;

    float Slt[4] = {0.f, 0.f, 0.f, 0.f};
    int   Sng[4] = {0, 0, 0, 0};

    #pragma unroll 2
    for (int j = 0; j < deg; j++) {
        int e = __ldg(&g_edgeC[s + j]);
        float4 l4 = __ldg(v2cNew + (size_t)e * B4 + col);
        float lam[4] = {l4.x, l4.y, l4.z, l4.w};
        float enc[4];
        #pragma unroll
        for (int i = 0; i < 4; i++) {
            float lm = fminf(fmaxf(lam[i], -CLIPV), CLIPV);
            int ng = (lm < 0.f) ? 1 : 0;
            float al = fminf(fmaxf(fabsf(lm), ABS_MIN), CLIPV);
            float lt = logtanh_half(al);           // < 0
            Slt[i] += lt;
            Sng[i] += ng;
            enc[i] = ng ? lt : -lt;                // sign bit = ng
        }
        if (j < DC_SMEM)
            senc[j][threadIdx.x] = make_float4(enc[0], enc[1], enc[2], enc[3]);
    }

    #pragma unroll 2
    for (int j = 0; j < deg; j++) {
        int e = __ldg(&g_edgeC[s + j]);
        int v = __ldg(vi + e);
        float lt[4]; int ng[4];
        if (j < DC_SMEM) {
            float4 e4 = senc[j][threadIdx.x];
            float enc[4] = {e4.x, e4.y, e4.z, e4.w};
            #pragma unroll
            for (int i = 0; i < 4; i++) {
                ng[i] = (enc[i] < 0.f) ? 1 : 0;
                lt[i] = -fabsf(enc[i]);
            }
        } else {
            float4 l4 = __ldg(v2cNew + (size_t)e * B4 + col);  // L1 hit
            float lam[4] = {l4.x, l4.y, l4.z, l4.w};
            #pragma unroll
            for (int i = 0; i < 4; i++) {
                float lm = fminf(fmaxf(lam[i], -CLIPV), CLIPV);
                ng[i] = (lm < 0.f) ? 1 : 0;
                float al = fminf(fmaxf(fabsf(lm), ABS_MIN), CLIPV);
                lt[i] = logtanh_half(al);
            }
        }

        float4 mc = __ldcs(mc2v + (size_t)e * B4 + col);
        float mcs[4] = {mc.x, mc.y, mc.z, mc.w};
        float os[4];
        #pragma unroll
        for (int i = 0; i < 4; i++) {
            float amp = fminf(Slt[i] - lt[i], 0.0f);
            int cnt = Sng[i] - ng[i];
            float y = __expf(amp) * (1.0f - EPSF);
            float h = __logf(__fdividef(1.0f + y, 1.0f - y));   // 2*atanh(y) >= 0
            unsigned hu = __float_as_uint(h) ^ ((unsigned)(cnt & 1) << 31);
            os[i] = omg * mcs[i] + g * __uint_as_float(hu);
        }
        float4 o = make_float4(os[0], os[1], os[2], os[3]);
        __stcs(outC2V + (size_t)e * B4 + col, o);

        float* dst = outM + (size_t)v * BB + col * 4;
        red_add_v4(dst, make_float4(We * o.x, We * o.y, We * o.z, We * o.w));
    }
}

// ---------------- launch ----------------
extern "C" void kernel_launch(void* const* d_in, const int* in_sizes, int n_in,
                              void* d_out, int out_size)
{
    (void)in_sizes; (void)n_in; (void)out_size;

    const float* chn  = (const float*)d_in[0];
    const float* mc2v = (const float*)d_in[1];
    const float* mv2c = (const float*)d_in[2];
    const float* Wi   = (const float*)d_in[3];
    const float* We   = (const float*)d_in[4];
    const float* gm   = (const float*)d_in[5];
    const int*   vi   = (const int*)d_in[6];
    const int*   ci   = (const int*)d_in[7];

    // outputs: (msg_C2V, msg_V2C, output)
    float* outC2V = (float*)d_out;
    float* outV2C = outC2V + (size_t)NE * BB;
    float* outM   = outV2C + (size_t)NE * BB;

    void *pcv, *pcc;
    cudaGetSymbolAddress(&pcv, g_cntV);
    cudaGetSymbolAddress(&pcc, g_cntC);
    cudaMemsetAsync(pcv, 0, sizeof(int) * NV, 0);
    cudaMemsetAsync(pcc, 0, sizeof(int) * NC, 0);

    kCount<<<NE / 256, 256>>>(vi, ci);
    kScan<<<2, 1024>>>();
    kFill<<<NE / 256, 256>>>(vi, ci);

    kV<<<dim3(NV, 2), 128>>>((const float4*)chn, (const float4*)mc2v,
                             (const float4*)mv2c, Wi, We, gm,
                             (float4*)outV2C, (float4*)outM);
    kH<<<dim3(NC, 2), 128>>>((const float4*)outV2C, (const float4*)mc2v,
                             vi, We, gm, (float4*)outC2V, outM);
}

// round 13
// speedup vs baseline: 1.2016x; 1.0616x over previous
#include <cuda_runtime.h>

// ---------------- problem constants ----------------
#define NV 16384
#define NC 8192
#define NE 65536
#define BB 1024
#define B4 256            // BB/4 float4 per row
#define CLIPV 15.0f
#define EPSF 1e-6f
#define ABS_MIN 6.1180464e-07f   // -log(tanh(15/2))

#define DV_REG 4          // reg-cached edges per variable
#define DC_REG 4          // reg-cached edges per check

// ---------------- scratch (static device globals) ----------------
__device__ int g_cntV[NV];
__device__ int g_cntC[NC];
__device__ int g_rowV[NV + 1];
__device__ int g_rowC[NC + 1];
__device__ int g_curV[NV];
__device__ int g_curC[NC];
__device__ int g_edgeV[NE];
__device__ int g_edgeC[NE];

// log(tanh(x/2)), x in [ABS_MIN, 15], 1 MUFU + FMAs  (always < 0)
__device__ __forceinline__ float logtanh_fast(float x) {
    if (x > 0.8f) {
        // -2*atanh(u), u = e^-x <= 0.449; odd series through u^11
        // abs err < 5e-6 at the boundary, exact as x grows
        float u = __expf(-x);
        float u2 = u * u;
        float p = 0.090909091f;                    // 1/11
        p = 0.111111111f + u2 * p;                 // 1/9
        p = 0.142857143f + u2 * p;                 // 1/7
        p = 0.2f         + u2 * p;                 // 1/5
        p = 0.333333333f + u2 * p;                 // 1/3
        p = 1.0f         + u2 * p;
        return -2.0f * u * p;
    } else {
        // log(z) + z^2(-1/3 + z^2(7/90 - 0.0218854 z^2)), z = x/2 <= 0.4
        // abs err < 5e-6 on (0, 0.8]
        float z = 0.5f * x;
        float z2 = z * z;
        float q = -0.33333333f + z2 * (0.077777778f - 0.021885430f * z2);
        return __logf(z) + z2 * q;
    }
}

__device__ __forceinline__ void red_add_v4(float* p, float4 v) {
    asm volatile("red.global.add.v4.f32 [%0], {%1, %2, %3, %4};"
                 :: "l"(p), "f"(v.x), "f"(v.y), "f"(v.z), "f"(v.w) : "memory");
}

// ---------------- CSR build ----------------
__global__ void __launch_bounds__(256) kCount(const int* __restrict__ vi,
                                              const int* __restrict__ ci)
{
    int e = blockIdx.x * 256 + threadIdx.x;
    if (e < NE) {
        atomicAdd(&g_cntV[__ldg(vi + e)], 1);
        atomicAdd(&g_cntC[__ldg(ci + e)], 1);
    }
}

__global__ void __launch_bounds__(1024) kScan()
{
    const bool isV = (blockIdx.x == 0);
    const int N = isV ? NV : NC;
    int* cnt = isV ? g_cntV : g_cntC;
    int* row = isV ? g_rowV : g_rowC;
    int* cur = isV ? g_curV : g_curC;
    const int CH = N / 1024;
    int t = threadIdx.x;
    int base = t * CH;
    int local[16];
    int s = 0;
    for (int i = 0; i < CH; i++) { local[i] = s; s += cnt[base + i]; }
    __shared__ int sm[1024];
    sm[t] = s;
    __syncthreads();
    for (int d = 1; d < 1024; d <<= 1) {
        int x = (t >= d) ? sm[t - d] : 0;
        __syncthreads();
        sm[t] += x;
        __syncthreads();
    }
    int excl = (t == 0) ? 0 : sm[t - 1];
    for (int i = 0; i < CH; i++) {
        row[base + i] = excl + local[i];
        cur[base + i] = excl + local[i];
    }
    if (t == 1023) row[N] = sm[1023];
}

__global__ void __launch_bounds__(256) kFill(const int* __restrict__ vi,
                                             const int* __restrict__ ci)
{
    int e = blockIdx.x * 256 + threadIdx.x;
    if (e < NE) {
        int p = atomicAdd(&g_curV[__ldg(vi + e)], 1);
        g_edgeV[p] = e;
        int q = atomicAdd(&g_curC[__ldg(ci + e)], 1);
        g_edgeC[q] = e;
    }
}

// ---------------- V step (also initializes outM = Wi*chn) ----------------
__global__ void __launch_bounds__(128) kV(
    const float4* __restrict__ chn, const float4* __restrict__ mc2v,
    const float4* __restrict__ mv2c,
    const float* __restrict__ Wi_p, const float* __restrict__ We_p,
    const float* __restrict__ gm_p,
    float4* __restrict__ outV2C, float4* __restrict__ outM)
{
    int v = blockIdx.x;
    int col = blockIdx.y * 128 + threadIdx.x;   // float4 column
    int s = __ldg(&g_rowV[v]), e1 = __ldg(&g_rowV[v + 1]);
    int deg = e1 - s;

    float Wi = __ldg(Wi_p), We = __ldg(We_p), g = __ldg(gm_p);
    float omg = 1.0f - g;
    float4 ch = __ldcs(chn + (size_t)v * B4 + col);

    // init marginal output (REDs from kH accumulate on top)
    outM[(size_t)v * B4 + col] =
        make_float4(Wi * ch.x, Wi * ch.y, Wi * ch.z, Wi * ch.w);
    if (deg == 0) return;

    float4 mreg[DV_REG];
    float sx = 0.f, sy = 0.f, sz = 0.f, sw = 0.f;
    #pragma unroll 4
    for (int j = 0; j < deg; j++) {
        int e = __ldg(&g_edgeV[s + j]);
        float4 m = __ldg(mc2v + (size_t)e * B4 + col);
        if (j < DV_REG) mreg[j] = m;
        sx += m.x; sy += m.y; sz += m.z; sw += m.w;
    }

    float ellx = Wi * ch.x, elly = Wi * ch.y, ellz = Wi * ch.z, ellw = Wi * ch.w;

    #pragma unroll 4
    for (int j = 0; j < deg; j++) {
        int e = __ldg(&g_edgeV[s + j]);
        float4 m = (j < DV_REG) ? mreg[j]
                                : __ldg(mc2v + (size_t)e * B4 + col); // L1 hit
        float4 mv = __ldcs(mv2c + (size_t)e * B4 + col);
        float4 o;
        o.x = omg * mv.x + g * (ellx + We * (sx - m.x));
        o.y = omg * mv.y + g * (elly + We * (sy - m.y));
        o.z = omg * mv.z + g * (ellz + We * (sz - m.z));
        o.w = omg * mv.w + g * (ellw + We * (sw - m.w));
        outV2C[(size_t)e * B4 + col] = o;
    }
}

// ---------------- H step: no smem, reg cache, fast-poly logtanh ----------
__global__ void __launch_bounds__(128) kH(
    const float4* __restrict__ v2cNew, const float4* __restrict__ mc2v,
    const int* __restrict__ vi,
    const float* __restrict__ We_p, const float* __restrict__ gm_p,
    float4* __restrict__ outC2V, float* __restrict__ outM)
{
    int c = blockIdx.x;
    int col = blockIdx.y * 128 + threadIdx.x;
    int s = __ldg(&g_rowC[c]), e1 = __ldg(&g_rowC[c + 1]);
    int deg = e1 - s;
    if (deg == 0) return;

    float We = __ldg(We_p), g = __ldg(gm_p);
    float omg = 1.0f - g;

    float Slt[4] = {0.f, 0.f, 0.f, 0.f};
    int   Sng[4] = {0, 0, 0, 0};
    float4 encreg[DC_REG];   // |enc| = -lt (>0); sign bit set iff lam<0

    #pragma unroll 2
    for (int j = 0; j < deg; j++) {
        int e = __ldg(&g_edgeC[s + j]);
        float4 l4 = __ldg(v2cNew + (size_t)e * B4 + col);
        float lam[4] = {l4.x, l4.y, l4.z, l4.w};
        float enc[4];
        #pragma unroll
        for (int i = 0; i < 4; i++) {
            float lm = fminf(fmaxf(lam[i], -CLIPV), CLIPV);
            int ng = (lm < 0.f) ? 1 : 0;
            float al = fminf(fmaxf(fabsf(lm), ABS_MIN), CLIPV);
            float lt = logtanh_fast(al);           // < 0
            Slt[i] += lt;
            Sng[i] += ng;
            enc[i] = ng ? lt : -lt;                // sign bit = ng
        }
        if (j < DC_REG)
            encreg[j] = make_float4(enc[0], enc[1], enc[2], enc[3]);
    }

    #pragma unroll 2
    for (int j = 0; j < deg; j++) {
        int e = __ldg(&g_edgeC[s + j]);
        int v = __ldg(vi + e);
        float lt[4]; int ng[4];
        if (j < DC_REG) {
            float4 e4 = encreg[j];
            float enc[4] = {e4.x, e4.y, e4.z, e4.w};
            #pragma unroll
            for (int i = 0; i < 4; i++) {
                ng[i] = (enc[i] < 0.f) ? 1 : 0;
                lt[i] = -fabsf(enc[i]);
            }
        } else {
            float4 l4 = __ldg(v2cNew + (size_t)e * B4 + col);  // L1 hit
            float lam[4] = {l4.x, l4.y, l4.z, l4.w};
            #pragma unroll
            for (int i = 0; i < 4; i++) {
                float lm = fminf(fmaxf(lam[i], -CLIPV), CLIPV);
                ng[i] = (lm < 0.f) ? 1 : 0;
                float al = fminf(fmaxf(fabsf(lm), ABS_MIN), CLIPV);
                lt[i] = logtanh_fast(al);
            }
        }

        float4 mc = __ldcs(mc2v + (size_t)e * B4 + col);
        float mcs[4] = {mc.x, mc.y, mc.z, mc.w};
        float os[4];
        #pragma unroll
        for (int i = 0; i < 4; i++) {
            float amp = fminf(Slt[i] - lt[i], 0.0f);
            int cnt = Sng[i] - ng[i];
            float y = __expf(amp) * (1.0f - EPSF);
            float h = __logf(__fdividef(1.0f + y, 1.0f - y));   // 2*atanh(y) >= 0
            unsigned hu = __float_as_uint(h) ^ ((unsigned)(cnt & 1) << 31);
            os[i] = omg * mcs[i] + g * __uint_as_float(hu);
        }
        float4 o = make_float4(os[0], os[1], os[2], os[3]);
        __stcs(outC2V + (size_t)e * B4 + col, o);

        float* dst = outM + (size_t)v * BB + col * 4;
        red_add_v4(dst, make_float4(We * o.x, We * o.y, We * o.z, We * o.w));
    }
}

// ---------------- launch ----------------
extern "C" void kernel_launch(void* const* d_in, const int* in_sizes, int n_in,
                              void* d_out, int out_size)
{
    (void)in_sizes; (void)n_in; (void)out_size;

    const float* chn  = (const float*)d_in[0];
    const float* mc2v = (const float*)d_in[1];
    const float* mv2c = (const float*)d_in[2];
    const float* Wi   = (const float*)d_in[3];
    const float* We   = (const float*)d_in[4];
    const float* gm   = (const float*)d_in[5];
    const int*   vi   = (const int*)d_in[6];
    const int*   ci   = (const int*)d_in[7];

    // outputs: (msg_C2V, msg_V2C, output)
    float* outC2V = (float*)d_out;
    float* outV2C = outC2V + (size_t)NE * BB;
    float* outM   = outV2C + (size_t)NE * BB;

    void *pcv, *pcc;
    cudaGetSymbolAddress(&pcv, g_cntV);
    cudaGetSymbolAddress(&pcc, g_cntC);
    cudaMemsetAsync(pcv, 0, sizeof(int) * NV, 0);
    cudaMemsetAsync(pcc, 0, sizeof(int) * NC, 0);

    kCount<<<NE / 256, 256>>>(vi, ci);
    kScan<<<2, 1024>>>();
    kFill<<<NE / 256, 256>>>(vi, ci);

    kV<<<dim3(NV, 2), 128>>>((const float4*)chn, (const float4*)mc2v,
                             (const float4*)mv2c, Wi, We, gm,
                             (float4*)outV2C, (float4*)outM);
    kH<<<dim3(NC, 2), 128>>>((const float4*)outV2C, (const float4*)mc2v,
                             vi, We, gm, (float4*)outC2V, outM);
}